// round 2
// baseline (speedup 1.0000x reference)
#include <cuda_runtime.h>
#include <math.h>

#define SLEN 4096
#define EDIM 256
#define HDIM 256
#define TAGS 32
#define NEGV (-10000.0f)
#define NBLK 16        // LSTM blocks per direction
#define STARTTAG 30
#define STOPTAG  31

// ---------------- scratch (device globals; no allocation allowed) ----------------
__device__ float g_xg[2][SLEN][4 * HDIM];          // 32 MB : precomputed input gates
__device__ float g_hs[2][SLEN][HDIM];              // 8 MB  : hidden states (scan order)
__device__ float g_feats[SLEN][TAGS];              // 512 KB
__device__ __align__(16) float g_hbuf[2][2][HDIM]; // double-buffered h exchange
__device__ int   g_cnt[2][SLEN];                   // per-step arrival counters

__device__ __forceinline__ float sigmoidf_(float x) { return 1.0f / (1.0f + expf(-x)); }

// ---------------- K1: xg[d][t][r] = emb[sent_d(t)] . w_ih_d[r] + b_d[r] ----------
__global__ void k1_xg(const int* __restrict__ sent,
                      const float* __restrict__ embedding,
                      const float* __restrict__ w_ih_f, const float* __restrict__ b_f,
                      const float* __restrict__ w_ih_b, const float* __restrict__ b_b)
{
    __shared__ __align__(16) float embs[16][EDIM];
    const int d  = blockIdx.z;
    const int t0 = blockIdx.x * 16;
    const int n  = blockIdx.y * 256 + threadIdx.x;   // gate row 0..1023

    for (int tt = 0; tt < 16; tt++) {
        int pos  = t0 + tt;
        int spos = d ? (SLEN - 1 - pos) : pos;
        int tok  = sent[spos];
        embs[tt][threadIdx.x] = embedding[(size_t)tok * EDIM + threadIdx.x];
    }
    __syncthreads();

    const float* W = d ? w_ih_b : w_ih_f;
    const float* B = d ? b_b    : b_f;
    float acc[16];
    float bias = B[n];
#pragma unroll
    for (int tt = 0; tt < 16; tt++) acc[tt] = bias;

    const float4* Wr = (const float4*)(W + (size_t)n * EDIM);
#pragma unroll 4
    for (int e4 = 0; e4 < EDIM / 4; e4++) {
        float4 w4 = __ldg(&Wr[e4]);
#pragma unroll
        for (int tt = 0; tt < 16; tt++) {
            float4 ev = *(const float4*)&embs[tt][e4 * 4];
            float a = acc[tt];
            a = fmaf(w4.x, ev.x, a);
            a = fmaf(w4.y, ev.y, a);
            a = fmaf(w4.z, ev.z, a);
            a = fmaf(w4.w, ev.w, a);
            acc[tt] = a;
        }
    }
#pragma unroll
    for (int tt = 0; tt < 16; tt++) g_xg[d][t0 + tt][n] = acc[tt];
}

// ---------------- K2: persistent bidirectional LSTM recurrence -------------------
// 2 dirs x 16 blocks x 512 threads. Warp wi owns h-index j = blk*16 + wi.
// Each lane holds 4 gate rows x 8 cols of W_hh in registers.
__global__ void __launch_bounds__(512, 1) k2_lstm(
    const float* __restrict__ h0, const float* __restrict__ c0,
    const float* __restrict__ w_hh_f, const float* __restrict__ w_hh_b)
{
    const int d    = blockIdx.x >> 4;
    const int blk  = blockIdx.x & 15;
    const int wi   = threadIdx.x >> 5;
    const int lane = threadIdx.x & 31;
    const int j    = blk * 16 + wi;          // 0..255

    const float* W = d ? w_hh_b : w_hh_f;
    float4 w4[4][2];
#pragma unroll
    for (int r = 0; r < 4; r++) {
        const float4* p = (const float4*)(W + ((size_t)(r * HDIM + j)) * HDIM + lane * 8);
        w4[r][0] = __ldg(&p[0]);
        w4[r][1] = __ldg(&p[1]);
    }

    float cst = 0.0f;
    if (lane == 0) cst = c0[d * HDIM + j];

    for (int t = 0; t < SLEN; t++) {
        // prefetch xg for this step (independent of the barrier)
        float xgv = 0.0f;
        if (lane < 4) xgv = __ldg(&g_xg[d][t][lane * HDIM + j]);

        if (t > 0) {
            if (threadIdx.x == 0) {
                volatile int* c = &g_cnt[d][t - 1];
                while (*c != NBLK) { }
            }
            __syncthreads();
        }

        const float4* hp = (t == 0) ? (const float4*)(h0 + d * HDIM)
                                    : (const float4*)g_hbuf[d][(t - 1) & 1];
        float4 ha = __ldcv(hp + lane * 2);
        float4 hb = __ldcv(hp + lane * 2 + 1);

        float acc[4];
#pragma unroll
        for (int r = 0; r < 4; r++) {
            float a;
            a = w4[r][0].x * ha.x;
            a = fmaf(w4[r][0].y, ha.y, a);
            a = fmaf(w4[r][0].z, ha.z, a);
            a = fmaf(w4[r][0].w, ha.w, a);
            a = fmaf(w4[r][1].x, hb.x, a);
            a = fmaf(w4[r][1].y, hb.y, a);
            a = fmaf(w4[r][1].z, hb.z, a);
            a = fmaf(w4[r][1].w, hb.w, a);
            acc[r] = a;
        }
#pragma unroll
        for (int ofs = 16; ofs > 0; ofs >>= 1) {
#pragma unroll
            for (int r = 0; r < 4; r++)
                acc[r] += __shfl_xor_sync(0xffffffffu, acc[r], ofs);
        }

        float val = 0.0f;
        if (lane < 4) {
            float a = acc[lane] + xgv;          // gates: i(0) f(1) g(2) o(3)
            val = (lane == 2) ? tanhf(a) : sigmoidf_(a);
        }
        float iv = __shfl_sync(0xffffffffu, val, 0);
        float fv = __shfl_sync(0xffffffffu, val, 1);
        float gv = __shfl_sync(0xffffffffu, val, 2);
        float ov = __shfl_sync(0xffffffffu, val, 3);

        if (lane == 0) {
            cst = fv * cst + iv * gv;
            float hv = ov * tanhf(cst);
            g_hbuf[d][t & 1][j] = hv;
            g_hs[d][t][j]       = hv;
            __threadfence();                    // writer-side release (belt)
        }
        __syncthreads();
        if (threadIdx.x == 0) {
            __threadfence();                    // release before arrive
            atomicAdd(&g_cnt[d][t], 1);         // unused result -> RED
        }
    }
}

// ---------------- K3: feats[t] = [hs_f[t], hs_b[S-1-t]] @ lin_w^T + lin_b --------
__global__ void k3_feats(const float* __restrict__ lin_w, const float* __restrict__ lin_b)
{
    __shared__ __align__(16) float cat[2 * HDIM];
    const int t   = blockIdx.x;
    const int tid = threadIdx.x;                // 256
    cat[tid]        = g_hs[0][t][tid];
    cat[HDIM + tid] = g_hs[1][SLEN - 1 - t][tid];
    __syncthreads();

    const int n = tid >> 3, seg = tid & 7;
    const float* w  = lin_w + (size_t)n * 2 * HDIM + seg * 64;
    const float* cc = cat + seg * 64;
    float s = 0.0f;
#pragma unroll 16
    for (int k = 0; k < 64; k++) s = fmaf(w[k], cc[k], s);
    s += __shfl_xor_sync(0xffffffffu, s, 1);
    s += __shfl_xor_sync(0xffffffffu, s, 2);
    s += __shfl_xor_sync(0xffffffffu, s, 4);
    if (seg == 0) g_feats[t][n] = s + lin_b[n];
}

// ---------------- K4: Viterbi forward + backtrack (bps kept in SMEM) -------------
__global__ void __launch_bounds__(1024, 1) k4_viterbi(
    const float* __restrict__ trans, float* __restrict__ out, int out_size)
{
    extern __shared__ unsigned char bps[];      // SLEN*TAGS bytes = 128 KB
    __shared__ float fv_s[2][TAGS];
    __shared__ float s_score;
    __shared__ int   s_last;

    const int tid = threadIdx.x;
    const int n = tid >> 5, p = tid & 31;       // warp = next-tag, lane = prev-tag
    const float tr = trans[n * TAGS + p];

    if (tid < TAGS) fv_s[0][tid] = (tid == STARTTAG) ? 0.0f : NEGV;
    __syncthreads();

    for (int t = 0; t < SLEN; t++) {
        const int pr = t & 1;
        float feat = 0.0f;
        if (p == 0) feat = g_feats[t][n];       // overlaps with reduction latency

        float v = fv_s[pr][p] + tr;
        int bi = p;
#pragma unroll
        for (int ofs = 16; ofs > 0; ofs >>= 1) {
            float ov = __shfl_down_sync(0xffffffffu, v, ofs);
            int   oi = __shfl_down_sync(0xffffffffu, bi, ofs);
            if (ov > v || (ov == v && oi < bi)) { v = ov; bi = oi; }  // first-max tie-break
        }
        if (p == 0) {
            fv_s[pr ^ 1][n] = v + feat;
            bps[t * TAGS + n] = (unsigned char)bi;
        }
        __syncthreads();
    }

    if (tid < 32) {                             // final = fv + transitions[STOP]
        float v = fv_s[0][p] + trans[STOPTAG * TAGS + p];
        int bi = p;
#pragma unroll
        for (int ofs = 16; ofs > 0; ofs >>= 1) {
            float ov = __shfl_down_sync(0xffffffffu, v, ofs);
            int   oi = __shfl_down_sync(0xffffffffu, bi, ofs);
            if (ov > v || (ov == v && oi < bi)) { v = ov; bi = oi; }
        }
        if (p == 0) { s_score = v; s_last = bi; }
    }
    __syncthreads();

    if (tid == 0) {
        const int off = (out_size > SLEN) ? 1 : 0;
        if (off) out[0] = s_score;
        int cur = s_last;
        for (int t = SLEN - 1; t >= 0; t--) {   // path[t]; then hop to t-1
            int idx = off + t;
            if (idx < out_size) out[idx] = (float)cur;
            cur = bps[t * TAGS + cur];
        }
    }
}

// ---------------- launch ----------------------------------------------------------
extern "C" void kernel_launch(void* const* d_in, const int* in_sizes, int n_in,
                              void* d_out, int out_size)
{
    (void)in_sizes; (void)n_in;
    const int*   sent      = (const int*)  d_in[0];
    const float* h0        = (const float*)d_in[1];
    const float* c0        = (const float*)d_in[2];
    const float* embedding = (const float*)d_in[3];
    const float* w_ih_f    = (const float*)d_in[4];
    const float* w_hh_f    = (const float*)d_in[5];
    const float* b_f       = (const float*)d_in[6];
    const float* w_ih_b    = (const float*)d_in[7];
    const float* w_hh_b    = (const float*)d_in[8];
    const float* b_b       = (const float*)d_in[9];
    const float* lin_w     = (const float*)d_in[10];
    const float* lin_b     = (const float*)d_in[11];
    const float* trans     = (const float*)d_in[12];

    // reset per-step barrier counters (captured into the graph, runs every replay)
    void* cntp = nullptr;
    cudaGetSymbolAddress(&cntp, g_cnt);
    cudaMemsetAsync(cntp, 0, sizeof(int) * 2 * SLEN, 0);

    dim3 g1(SLEN / 16, 4, 2);
    k1_xg<<<g1, 256>>>(sent, embedding, w_ih_f, b_f, w_ih_b, b_b);
    k2_lstm<<<2 * NBLK, 512>>>(h0, c0, w_hh_f, w_hh_b);
    k3_feats<<<SLEN, 256>>>(lin_w, lin_b);

    cudaFuncSetAttribute(k4_viterbi, cudaFuncAttributeMaxDynamicSharedMemorySize,
                         SLEN * TAGS);
    k4_viterbi<<<1, 1024, SLEN * TAGS>>>(trans, (float*)d_out, out_size);
}